// round 10
// baseline (speedup 1.0000x reference)
#include <cuda_runtime.h>
#include <math.h>
#include <stdint.h>

#define N_TOK 1024
#define DIMV  512
#define HEADS 8
#define DH    64
#define JPAD  1088          // 17*64 = 34*32
#define INV_EPS 10.0f
#define EPSF    0.1f
#define LOGK    2.0794415416798357f
#define CD_ITERS 50

// ---------------- scratch: interleaved {hi,lo} tf32-split float2 planes ----------------
__device__ __align__(16) float2 g_xn2[N_TOK * DIMV];
__device__ __align__(16) float2 g_w2 [512 * 1536];
__device__ __align__(16) float2 g_wo2[512 * 512];
__device__ __align__(16) float2 g_q2 [HEADS * N_TOK * DH];
__device__ __align__(16) float2 g_k2 [HEADS * JPAD * DH];
__device__ __align__(16) float2 g_v2 [HEADS * JPAD * DH];
__device__ __align__(16) float  g_s  [HEADS * N_TOK * JPAD];
__device__ __align__(16) float  g_o  [N_TOK * DIMV];
__device__ __align__(16) float  g_o2 [N_TOK * DIMV];

// ---------------- tf32 helpers ----------------
__device__ __forceinline__ float tf32_rna(float x) {
    uint32_t r; asm("cvt.rna.tf32.f32 %0, %1;" : "=r"(r) : "f"(x));
    return __uint_as_float(r);
}
__device__ __forceinline__ float2 split_tf2(float x) {
    float hi = tf32_rna(x);
    float lo = tf32_rna(x - hi);
    return make_float2(hi, lo);
}
__device__ __forceinline__ void mma8(float* d, const float* a, const float* b) {
    asm volatile(
        "mma.sync.aligned.m16n8k8.row.col.f32.tf32.tf32.f32 "
        "{%0,%1,%2,%3}, {%4,%5,%6,%7}, {%8,%9}, {%0,%1,%2,%3};"
        : "+f"(d[0]), "+f"(d[1]), "+f"(d[2]), "+f"(d[3])
        : "r"(__float_as_uint(a[0])), "r"(__float_as_uint(a[1])),
          "r"(__float_as_uint(a[2])), "r"(__float_as_uint(a[3])),
          "r"(__float_as_uint(b[0])), "r"(__float_as_uint(b[1])));
}

// ---------------- block reduction ----------------
__device__ __forceinline__ float block_sum_256(float v, float* red) {
#pragma unroll
    for (int o = 16; o; o >>= 1) v += __shfl_xor_sync(0xffffffffu, v, o);
    __syncthreads();
    if ((threadIdx.x & 31) == 0) red[threadIdx.x >> 5] = v;
    __syncthreads();
    v = red[threadIdx.x & 7];
#pragma unroll
    for (int o = 4; o; o >>= 1) v += __shfl_xor_sync(0xffffffffu, v, o);
    return v;
}

// ---------------- fused LayerNorm + null-kv/pad fill ----------------
__global__ void ln_fill_kernel(const float* __restrict__ x, const float* __restrict__ gam,
                               const float* __restrict__ bet,
                               const float* __restrict__ null_kv) {
    if (blockIdx.x >= 1024) {
        const int idx = (blockIdx.x - 1024) * 256 + threadIdx.x;
        const int h = idx >> 12;
        const int r = (idx >> 6) & 63;
        const int d = idx & 63;
        if (r < 2) {
            g_k2[(h * JPAD + r) * DH + d] = split_tf2(null_kv[((0 * HEADS + h) * 2 + r) * DH + d]);
            g_v2[(h * JPAD + r) * DH + d] = split_tf2(null_kv[((1 * HEADS + h) * 2 + r) * DH + d]);
        } else {
            const int j = 1024 + r;
            g_k2[(h * JPAD + j) * DH + d] = make_float2(0.f, 0.f);
            g_v2[(h * JPAD + j) * DH + d] = make_float2(0.f, 0.f);
        }
        return;
    }
    __shared__ float red[8];
    const int row = blockIdx.x;
    const int tid = threadIdx.x;
    const float v0 = x[row * DIMV + tid];
    const float v1 = x[row * DIMV + tid + 256];
    float s  = v0 + v1;
    float sq = v0 * v0 + v1 * v1;
    s  = block_sum_256(s,  red);
    sq = block_sum_256(sq, red);
    const float mean = s * (1.0f / 512.0f);
    const float var  = sq * (1.0f / 512.0f) - mean * mean;
    const float rstd = rsqrtf(var + 1e-5f);
    g_xn2[row * DIMV + tid]       = split_tf2((v0 - mean) * rstd * gam[tid]       + bet[tid]);
    g_xn2[row * DIMV + tid + 256] = split_tf2((v1 - mean) * rstd * gam[tid + 256] + bet[tid + 256]);
}

// ---------------- split both weight matrices (interleaved) ----------------
__global__ void wsplit_kernel(const float* __restrict__ Wqkv, const float* __restrict__ Wout) {
    const int g4 = (blockIdx.x * 256 + threadIdx.x) * 4;
    if (g4 < 512 * 1536) {
        float4 v = *(const float4*)(Wqkv + g4);
        g_w2[g4 + 0] = split_tf2(v.x); g_w2[g4 + 1] = split_tf2(v.y);
        g_w2[g4 + 2] = split_tf2(v.z); g_w2[g4 + 3] = split_tf2(v.w);
    } else {
        const int o = g4 - 512 * 1536;
        float4 v = *(const float4*)(Wout + o);
        g_wo2[o + 0] = split_tf2(v.x); g_wo2[o + 1] = split_tf2(v.y);
        g_wo2[o + 2] = split_tf2(v.z); g_wo2[o + 3] = split_tf2(v.w);
    }
}

// ---------------- fragment gather helpers (conflict-free f2 layouts) ----------------
// A tile layout: A2[k][row], row-stride RS with RS % 16 == 4  -> banks 4*lq+grp distinct.
// B tile layout: B2[k][col], col-stride 68.

// ---------------- QKV GEMM: block 128x64, warp 32x32, tf32 x3 ----------------
__global__ void __launch_bounds__(256) gemm_qkv() {
    __shared__ float2 A2[16][132];
    __shared__ float2 B2[16][68];
    const int bx = blockIdx.x, by = blockIdx.y, tid = threadIdx.x;
    const int wid = tid >> 5, lane = tid & 31;
    const int wm = wid & 3, wn = wid >> 2;
    const int grp = lane >> 2, lq = lane & 3;
    const int arow = tid & 127, akh = (tid >> 7) << 3;
    const int bcol = tid & 63,  bkq = (tid >> 6) << 2;
    float acc[2][4][4] = {};

    for (int k0 = 0; k0 < 512; k0 += 16) {
        const float2* agp = g_xn2 + (by * 128 + arow) * 512 + k0 + akh;
#pragma unroll
        for (int c = 0; c < 8; c += 2) {
            float4 v = *(const float4*)(agp + c);
            A2[akh + c][arow]     = make_float2(v.x, v.y);
            A2[akh + c + 1][arow] = make_float2(v.z, v.w);
        }
#pragma unroll
        for (int c = 0; c < 4; c++)
            B2[bkq + c][bcol] = g_w2[(size_t)(k0 + bkq + c) * 1536 + bx * 64 + bcol];
        __syncthreads();
#pragma unroll
        for (int ks = 0; ks < 2; ks++) {
            const int kb = ks * 8;
            float a_h[2][4], a_l[2][4], b_h[4][2], b_l[4][2];
#pragma unroll
            for (int mt = 0; mt < 2; mt++) {
                const int mb = wm * 32 + mt * 16;
                float2 t;
                t = A2[kb + lq][mb + grp];         a_h[mt][0] = t.x; a_l[mt][0] = t.y;
                t = A2[kb + lq][mb + grp + 8];     a_h[mt][1] = t.x; a_l[mt][1] = t.y;
                t = A2[kb + lq + 4][mb + grp];     a_h[mt][2] = t.x; a_l[mt][2] = t.y;
                t = A2[kb + lq + 4][mb + grp + 8]; a_h[mt][3] = t.x; a_l[mt][3] = t.y;
            }
#pragma unroll
            for (int nt = 0; nt < 4; nt++) {
                const int nb = wn * 32 + nt * 8;
                float2 t;
                t = B2[kb + lq][nb + grp];     b_h[nt][0] = t.x; b_l[nt][0] = t.y;
                t = B2[kb + lq + 4][nb + grp]; b_h[nt][1] = t.x; b_l[nt][1] = t.y;
            }
#pragma unroll
            for (int mt = 0; mt < 2; mt++)
#pragma unroll
                for (int nt = 0; nt < 4; nt++) {
                    mma8(acc[mt][nt], a_h[mt], b_l[nt]);
                    mma8(acc[mt][nt], a_l[mt], b_h[nt]);
                    mma8(acc[mt][nt], a_h[mt], b_h[nt]);
                }
        }
        __syncthreads();
    }
#pragma unroll
    for (int mt = 0; mt < 2; mt++)
#pragma unroll
        for (int nt = 0; nt < 4; nt++)
#pragma unroll
            for (int c = 0; c < 4; c++) {
                const int row = by * 128 + wm * 32 + mt * 16 + grp + ((c >> 1) << 3);
                const int col = bx * 64 + wn * 32 + nt * 8 + 2 * lq + (c & 1);
                const float val = acc[mt][nt][c];
                const int w = col >> 9, h = (col >> 6) & 7, d = col & 63;
                if (w == 0)      g_q2[(h * N_TOK + row) * DH + d] = split_tf2(val * 0.125f);
                else if (w == 1) g_k2[(h * JPAD + row + 2) * DH + d] = split_tf2(val);
                else             g_v2[(h * JPAD + row + 2) * DH + d] = split_tf2(val);
            }
}

// ---------------- sim = q.k^T: 128x64 causal tiles, warp 32x32 ----------------
__global__ void __launch_bounds__(256) sim_kernel() {
    const int f = blockIdx.x;
    const int h = blockIdx.y;
    int it2 = __float2int_rd(sqrtf((float)(f + 1))) - 1;
    while ((it2 + 1) * (it2 + 3) <= f) it2++;
    while (it2 * (it2 + 2) > f) it2--;
    const int jt = f - it2 * (it2 + 2);

    __shared__ float2 Q2[16][132];
    __shared__ float2 K2[16][68];
    const int tid = threadIdx.x;
    const int wid = tid >> 5, lane = tid & 31;
    const int wm = wid & 3, wn = wid >> 2;
    const int grp = lane >> 2, lq = lane & 3;
    const int qrow = tid & 127, qkh = (tid >> 7) << 3;
    const int kcol = tid & 63,  kkq = (tid >> 6) << 2;
    float acc[2][4][4] = {};

#pragma unroll
    for (int dc = 0; dc < 64; dc += 16) {
        const float2* qgp = g_q2 + ((h << 10) + it2 * 128 + qrow) * DH + dc + qkh;
#pragma unroll
        for (int c = 0; c < 8; c += 2) {
            float4 v = *(const float4*)(qgp + c);
            Q2[qkh + c][qrow]     = make_float2(v.x, v.y);
            Q2[qkh + c + 1][qrow] = make_float2(v.z, v.w);
        }
        const float2* kgp = g_k2 + (h * JPAD + jt * 64 + kcol) * DH + dc + kkq;
        {
            float4 v = *(const float4*)(kgp);
            K2[kkq + 0][kcol] = make_float2(v.x, v.y);
            K2[kkq + 1][kcol] = make_float2(v.z, v.w);
            v = *(const float4*)(kgp + 2);
            K2[kkq + 2][kcol] = make_float2(v.x, v.y);
            K2[kkq + 3][kcol] = make_float2(v.z, v.w);
        }
        __syncthreads();
#pragma unroll
        for (int ks = 0; ks < 2; ks++) {
            const int kb = ks * 8;
            float a_h[2][4], a_l[2][4], b_h[4][2], b_l[4][2];
#pragma unroll
            for (int mt = 0; mt < 2; mt++) {
                const int mb = wm * 32 + mt * 16;
                float2 t;
                t = Q2[kb + lq][mb + grp];         a_h[mt][0] = t.x; a_l[mt][0] = t.y;
                t = Q2[kb + lq][mb + grp + 8];     a_h[mt][1] = t.x; a_l[mt][1] = t.y;
                t = Q2[kb + lq + 4][mb + grp];     a_h[mt][2] = t.x; a_l[mt][2] = t.y;
                t = Q2[kb + lq + 4][mb + grp + 8]; a_h[mt][3] = t.x; a_l[mt][3] = t.y;
            }
#pragma unroll
            for (int nt = 0; nt < 4; nt++) {
                const int nb = wn * 32 + nt * 8;
                float2 t;
                t = K2[kb + lq][nb + grp];     b_h[nt][0] = t.x; b_l[nt][0] = t.y;
                t = K2[kb + lq + 4][nb + grp]; b_h[nt][1] = t.x; b_l[nt][1] = t.y;
            }
#pragma unroll
            for (int mt = 0; mt < 2; mt++)
#pragma unroll
                for (int nt = 0; nt < 4; nt++) {
                    mma8(acc[mt][nt], a_h[mt], b_l[nt]);
                    mma8(acc[mt][nt], a_l[mt], b_h[nt]);
                    mma8(acc[mt][nt], a_h[mt], b_h[nt]);
                }
        }
        __syncthreads();
    }
#pragma unroll
    for (int mt = 0; mt < 2; mt++)
#pragma unroll
        for (int nt = 0; nt < 4; nt++) {
            const int i0 = it2 * 128 + wm * 32 + mt * 16 + grp;
            const int j0 = jt * 64 + wn * 32 + nt * 8 + 2 * lq;
            float* s0 = g_s + (size_t)(h * N_TOK + i0) * JPAD + j0;
            *(float2*)s0 = make_float2(acc[mt][nt][0], acc[mt][nt][1]);
            float* s1 = g_s + (size_t)(h * N_TOK + i0 + 8) * JPAD + j0;
            *(float2*)s1 = make_float2(acc[mt][nt][2], acc[mt][nt][3]);
        }
}

// ---------------- coordinate descent (unchanged) ----------------
template<int MAXU>
__device__ __forceinline__ void cd_row(float* __restrict__ srow, int lane, int jmax,
                                       int nchunk, int chunks) {
    float E1[MAXU];
    float tm = -3.4e38f;
#pragma unroll
    for (int u = 0; u < MAXU; u++) {
        E1[u] = -3.4e38f;
        if (u < nchunk) {
            const int j = lane + u * 32;
            if (j < jmax) { E1[u] = srow[j]; tm = fmaxf(tm, E1[u]); }
        }
    }
#pragma unroll
    for (int o = 16; o; o >>= 1) tm = fmaxf(tm, __shfl_xor_sync(0xffffffffu, tm, o));
    const float m = tm;
#pragma unroll
    for (int u = 0; u < MAXU; u++)
        if (u < nchunk)
            E1[u] = (E1[u] > -3.0e38f) ? __expf((E1[u] - m) * INV_EPS) : 0.0f;

    float a = EPSF * (LOGK - __logf((float)jmax));

    for (int it = 1; it < CD_ITERS; it++) {
        const float w = __expf((a + m) * INV_EPS);
        float ls0 = 0.0f, ls1 = 0.0f;
#pragma unroll
        for (int u = 0; u < MAXU; u++) {
            if (u < nchunk) {
                const float e = E1[u];
                const float c = fminf(e, w * (e * e));
                if (u & 1) ls1 += c; else ls0 += c;
            }
        }
        float ls = ls0 + ls1;
#pragma unroll
        for (int o = 16; o; o >>= 1) ls += __shfl_xor_sync(0xffffffffu, ls, o);
        const float a_new = EPSF * LOGK - m - EPSF * __logf(ls);
        const float da = fabsf(a_new - a);
        a = a_new;
        if (da < 5e-7f) break;
    }

    const float w = __expf((a + m) * INV_EPS);
#pragma unroll
    for (int u = 0; u < MAXU + 3; u++) {
        if (u < chunks) {
            const int j = lane + u * 32;
            float val = 0.0f;
            if (u < MAXU && u < nchunk) {
                const float eu = w * E1[u];
                val = fminf(eu, eu * eu);
            }
            srow[j] = val;
        }
    }
}

__global__ void cd_kernel() {
    const int wg   = (blockIdx.x * blockDim.x + threadIdx.x) >> 5;
    const int lane = threadIdx.x & 31;
    const int i = wg >> 3, h = wg & 7;
    const int jmax = i + 3;
    const int nchunk = (jmax + 31) >> 5;
    const int chunks = ((i >> 6) + 2) << 1;
    float* srow = g_s + (size_t)(h * N_TOK + i) * JPAD;
    if (i < 254)      cd_row<8 >(srow, lane, jmax, nchunk, chunks);
    else if (i < 510) cd_row<16>(srow, lane, jmax, nchunk, chunks);
    else if (i < 766) cd_row<24>(srow, lane, jmax, nchunk, chunks);
    else              cd_row<33>(srow, lane, jmax, nchunk, chunks);
}

// ---------------- av = attn.v: block 64x64, warp 32x16, split-K ----------------
__global__ void __launch_bounds__(256) av_kernel() {
    const int it = blockIdx.x;
    const int h  = blockIdx.y;
    const int sp = blockIdx.z;
    const int T = it + 2;
    const int half = T >> 1;
    const int jc0 = (sp ? half : 0) * 2;
    const int jc1 = (sp ? T : half) * 2;

    __shared__ float2 P2[32][68];
    __shared__ float2 V2[32][68];
    const int tid = threadIdx.x;
    const int wid = tid >> 5, lane = tid & 31;
    const int wm = wid & 1, wn = wid >> 1;
    const int grp = lane >> 2, lq = lane & 3;
    const int pi = tid & 63, pjq = (tid >> 6) << 3;
    const int vd = tid & 63, vjq = (tid >> 6) << 3;
    float acc[2][2][4] = {};

    for (int jc = jc0; jc < jc1; jc++) {
        const float* pg = g_s + (size_t)(h * N_TOK + it * 64 + pi) * JPAD + jc * 32 + pjq;
        float4 v0 = *(const float4*)pg;
        float4 v1 = *(const float4*)(pg + 4);
        P2[pjq + 0][pi] = split_tf2(v0.x); P2[pjq + 1][pi] = split_tf2(v0.y);
        P2[pjq + 2][pi] = split_tf2(v0.z); P2[pjq + 3][pi] = split_tf2(v0.w);
        P2[pjq + 4][pi] = split_tf2(v1.x); P2[pjq + 5][pi] = split_tf2(v1.y);
        P2[pjq + 6][pi] = split_tf2(v1.z); P2[pjq + 7][pi] = split_tf2(v1.w);
#pragma unroll
        for (int c = 0; c < 8; c++)
            V2[vjq + c][vd] = g_v2[(h * JPAD + jc * 32 + vjq + c) * DH + vd];
        __syncthreads();
#pragma unroll
        for (int ks = 0; ks < 4; ks++) {
            const int kb = ks * 8;
            float a_h[2][4], a_l[2][4], b_h[2][2], b_l[2][2];
#pragma unroll
            for (int mt = 0; mt < 2; mt++) {
                const int mb = wm * 32 + mt * 16;
                float2 t;
                t = P2[kb + lq][mb + grp];         a_h[mt][0] = t.x; a_l[mt][0] = t.y;
                t = P2[kb + lq][mb + grp + 8];     a_h[mt][1] = t.x; a_l[mt][1] = t.y;
                t = P2[kb + lq + 4][mb + grp];     a_h[mt][2] = t.x; a_l[mt][2] = t.y;
                t = P2[kb + lq + 4][mb + grp + 8]; a_h[mt][3] = t.x; a_l[mt][3] = t.y;
            }
#pragma unroll
            for (int nt = 0; nt < 2; nt++) {
                const int nb = wn * 16 + nt * 8;
                float2 t;
                t = V2[kb + lq][nb + grp];     b_h[nt][0] = t.x; b_l[nt][0] = t.y;
                t = V2[kb + lq + 4][nb + grp]; b_h[nt][1] = t.x; b_l[nt][1] = t.y;
            }
#pragma unroll
            for (int mt = 0; mt < 2; mt++)
#pragma unroll
                for (int nt = 0; nt < 2; nt++) {
                    mma8(acc[mt][nt], a_h[mt], b_l[nt]);
                    mma8(acc[mt][nt], a_l[mt], b_h[nt]);
                    mma8(acc[mt][nt], a_h[mt], b_h[nt]);
                }
        }
        __syncthreads();
    }
    float* outp = sp ? g_o2 : g_o;
#pragma unroll
    for (int mt = 0; mt < 2; mt++)
#pragma unroll
        for (int nt = 0; nt < 2; nt++) {
            const int row = it * 64 + wm * 32 + mt * 16 + grp;
            const int d = wn * 16 + nt * 8 + 2 * lq;
            *(float2*)(outp + row * DIMV + h * DH + d) =
                make_float2(acc[mt][nt][0], acc[mt][nt][1]);
            *(float2*)(outp + (row + 8) * DIMV + h * DH + d) =
                make_float2(acc[mt][nt][2], acc[mt][nt][3]);
        }
}

// ---------------- out projection: block 64x64, warp 32x16 ----------------
__global__ void __launch_bounds__(256) gemm_proj(float* __restrict__ C) {
    __shared__ float2 A2[16][68];
    __shared__ float2 B2[16][68];
    const int bx = blockIdx.x, by = blockIdx.y, tid = threadIdx.x;
    const int wid = tid >> 5, lane = tid & 31;
    const int wm = wid & 1, wn = wid >> 1;
    const int grp = lane >> 2, lq = lane & 3;
    const int arow = tid & 63, akq = (tid >> 6) << 2;
    const int bcol = tid & 63, bkq = (tid >> 6) << 2;
    float acc[2][2][4] = {};

    for (int k0 = 0; k0 < 512; k0 += 16) {
        const int abase = (by * 64 + arow) * 512 + k0 + akq;
        float4 o1 = *(const float4*)(g_o + abase);
        float4 o2 = *(const float4*)(g_o2 + abase);
        A2[akq + 0][arow] = split_tf2(o1.x + o2.x);
        A2[akq + 1][arow] = split_tf2(o1.y + o2.y);
        A2[akq + 2][arow] = split_tf2(o1.z + o2.z);
        A2[akq + 3][arow] = split_tf2(o1.w + o2.w);
#pragma unroll
        for (int c = 0; c < 4; c++)
            B2[bkq + c][bcol] = g_wo2[(size_t)(k0 + bkq + c) * 512 + bx * 64 + bcol];
        __syncthreads();
#pragma unroll
        for (int ks = 0; ks < 2; ks++) {
            const int kb = ks * 8;
            float a_h[2][4], a_l[2][4], b_h[2][2], b_l[2][2];
#pragma unroll
            for (int mt = 0; mt < 2; mt++) {
                const int mb = wm * 32 + mt * 16;
                float2 t;
                t = A2[kb + lq][mb + grp];         a_h[mt][0] = t.x; a_l[mt][0] = t.y;
                t = A2[kb + lq][mb + grp + 8];     a_h[mt][1] = t.x; a_l[mt][1] = t.y;
                t = A2[kb + lq + 4][mb + grp];     a_h[mt][2] = t.x; a_l[mt][2] = t.y;
                t = A2[kb + lq + 4][mb + grp + 8]; a_h[mt][3] = t.x; a_l[mt][3] = t.y;
            }
#pragma unroll
            for (int nt = 0; nt < 2; nt++) {
                const int nb = wn * 16 + nt * 8;
                float2 t;
                t = B2[kb + lq][nb + grp];     b_h[nt][0] = t.x; b_l[nt][0] = t.y;
                t = B2[kb + lq + 4][nb + grp]; b_h[nt][1] = t.x; b_l[nt][1] = t.y;
            }
#pragma unroll
            for (int mt = 0; mt < 2; mt++)
#pragma unroll
                for (int nt = 0; nt < 2; nt++) {
                    mma8(acc[mt][nt], a_h[mt], b_l[nt]);
                    mma8(acc[mt][nt], a_l[mt], b_h[nt]);
                    mma8(acc[mt][nt], a_h[mt], b_h[nt]);
                }
        }
        __syncthreads();
    }
#pragma unroll
    for (int mt = 0; mt < 2; mt++)
#pragma unroll
        for (int nt = 0; nt < 2; nt++) {
            const int row = by * 64 + wm * 32 + mt * 16 + grp;
            const int col = bx * 64 + wn * 16 + nt * 8 + 2 * lq;
            *(float2*)(C + row * 512 + col) = make_float2(acc[mt][nt][0], acc[mt][nt][1]);
            *(float2*)(C + (row + 8) * 512 + col) = make_float2(acc[mt][nt][2], acc[mt][nt][3]);
        }
}

// ---------------- launch ----------------
extern "C" void kernel_launch(void* const* d_in, const int* in_sizes, int n_in,
                              void* d_out, int out_size) {
    const float* x       = (const float*)d_in[0];
    const float* w_qkv   = (const float*)d_in[1];
    const float* w_out   = (const float*)d_in[2];
    const float* null_kv = (const float*)d_in[3];
    const float* ln_g    = (const float*)d_in[4];
    const float* ln_b    = (const float*)d_in[5];
    float* out = (float*)d_out;

    ln_fill_kernel<<<1152, 256>>>(x, ln_g, ln_b, null_kv);
    wsplit_kernel <<<1024, 256>>>(w_qkv, w_out);
    gemm_qkv      <<<dim3(24, 8), 256>>>();
    sim_kernel    <<<dim3(80, HEADS), 256>>>();
    cd_kernel     <<<2048, 128>>>();
    av_kernel     <<<dim3(16, HEADS, 2), 256>>>();
    gemm_proj     <<<dim3(8, 16), 256>>>(out);
}

// round 11
// speedup vs baseline: 1.0747x; 1.0747x over previous
#include <cuda_runtime.h>
#include <math.h>
#include <stdint.h>

#define N_TOK 1024
#define DIMV  512
#define HEADS 8
#define DH    64
#define JPAD  1088          // 17*64 = 34*32
#define INV_EPS 10.0f
#define EPSF    0.1f
#define LOGK    2.0794415416798357f
#define CD_ITERS 50

// ---------------- scratch: interleaved {hi,lo} tf32-split float2 planes ----------------
__device__ __align__(16) float2 g_xn2[N_TOK * DIMV];
__device__ __align__(16) float2 g_w2 [512 * 1536];
__device__ __align__(16) float2 g_wo2[512 * 512];
__device__ __align__(16) float2 g_q2 [HEADS * N_TOK * DH];
__device__ __align__(16) float2 g_k2 [HEADS * JPAD * DH];
__device__ __align__(16) float2 g_v2 [HEADS * JPAD * DH];
__device__ __align__(16) float  g_s  [HEADS * N_TOK * JPAD];
__device__ __align__(16) float  g_o  [N_TOK * DIMV];
__device__ __align__(16) float  g_o2 [N_TOK * DIMV];
__device__ __align__(16) float  g_o3 [N_TOK * DIMV];
__device__ __align__(16) float  g_o4 [N_TOK * DIMV];

// ---------------- tf32 helpers ----------------
__device__ __forceinline__ float tf32_rna(float x) {
    uint32_t r; asm("cvt.rna.tf32.f32 %0, %1;" : "=r"(r) : "f"(x));
    return __uint_as_float(r);
}
__device__ __forceinline__ float2 split_tf2(float x) {
    float hi = tf32_rna(x);
    float lo = tf32_rna(x - hi);
    return make_float2(hi, lo);
}
__device__ __forceinline__ void mma8(float* d, const float* a, const float* b) {
    asm volatile(
        "mma.sync.aligned.m16n8k8.row.col.f32.tf32.tf32.f32 "
        "{%0,%1,%2,%3}, {%4,%5,%6,%7}, {%8,%9}, {%0,%1,%2,%3};"
        : "+f"(d[0]), "+f"(d[1]), "+f"(d[2]), "+f"(d[3])
        : "r"(__float_as_uint(a[0])), "r"(__float_as_uint(a[1])),
          "r"(__float_as_uint(a[2])), "r"(__float_as_uint(a[3])),
          "r"(__float_as_uint(b[0])), "r"(__float_as_uint(b[1])));
}

// Shared mma stage: block 64x64, 8 warps (wm = wid&3 -> 16 rows, wn = wid>>2 -> 32 cols),
// warp tile 16x32, acc[4][4]. A2/B2: [k16][64+4pad] float2 {hi,lo}, stride 68 (== 4 mod 16
// -> conflict-free fragment gathers per 64-bit phase).
__device__ __forceinline__ void mma_stage(const float2 (*A2)[68], const float2 (*B2)[68],
                                          int wm, int wn, int grp, int lq, float acc[4][4]) {
#pragma unroll
    for (int ks = 0; ks < 2; ks++) {
        const int kb = ks * 8;
        const int mb = wm * 16;
        float a_h[4], a_l[4];
        float2 t;
        t = A2[kb + lq][mb + grp];         a_h[0] = t.x; a_l[0] = t.y;
        t = A2[kb + lq][mb + grp + 8];     a_h[1] = t.x; a_l[1] = t.y;
        t = A2[kb + lq + 4][mb + grp];     a_h[2] = t.x; a_l[2] = t.y;
        t = A2[kb + lq + 4][mb + grp + 8]; a_h[3] = t.x; a_l[3] = t.y;
#pragma unroll
        for (int nt = 0; nt < 4; nt++) {
            const int nb = wn * 32 + nt * 8;
            float b_h[2], b_l[2];
            t = B2[kb + lq][nb + grp];     b_h[0] = t.x; b_l[0] = t.y;
            t = B2[kb + lq + 4][nb + grp]; b_h[1] = t.x; b_l[1] = t.y;
            mma8(acc[nt], a_h, b_l);
            mma8(acc[nt], a_l, b_h);
            mma8(acc[nt], a_h, b_h);
        }
    }
}

// ---------------- block reduction ----------------
__device__ __forceinline__ float block_sum_256(float v, float* red) {
#pragma unroll
    for (int o = 16; o; o >>= 1) v += __shfl_xor_sync(0xffffffffu, v, o);
    __syncthreads();
    if ((threadIdx.x & 31) == 0) red[threadIdx.x >> 5] = v;
    __syncthreads();
    v = red[threadIdx.x & 7];
#pragma unroll
    for (int o = 4; o; o >>= 1) v += __shfl_xor_sync(0xffffffffu, v, o);
    return v;
}

// ---------------- fused LayerNorm + null-kv/pad fill ----------------
__global__ void ln_fill_kernel(const float* __restrict__ x, const float* __restrict__ gam,
                               const float* __restrict__ bet,
                               const float* __restrict__ null_kv) {
    if (blockIdx.x >= 1024) {
        const int idx = (blockIdx.x - 1024) * 256 + threadIdx.x;
        const int h = idx >> 12;
        const int r = (idx >> 6) & 63;
        const int d = idx & 63;
        if (r < 2) {
            g_k2[(h * JPAD + r) * DH + d] = split_tf2(null_kv[((0 * HEADS + h) * 2 + r) * DH + d]);
            g_v2[(h * JPAD + r) * DH + d] = split_tf2(null_kv[((1 * HEADS + h) * 2 + r) * DH + d]);
        } else {
            const int j = 1024 + r;
            g_k2[(h * JPAD + j) * DH + d] = make_float2(0.f, 0.f);
            g_v2[(h * JPAD + j) * DH + d] = make_float2(0.f, 0.f);
        }
        return;
    }
    __shared__ float red[8];
    const int row = blockIdx.x;
    const int tid = threadIdx.x;
    const float v0 = x[row * DIMV + tid];
    const float v1 = x[row * DIMV + tid + 256];
    float s  = v0 + v1;
    float sq = v0 * v0 + v1 * v1;
    s  = block_sum_256(s,  red);
    sq = block_sum_256(sq, red);
    const float mean = s * (1.0f / 512.0f);
    const float var  = sq * (1.0f / 512.0f) - mean * mean;
    const float rstd = rsqrtf(var + 1e-5f);
    g_xn2[row * DIMV + tid]       = split_tf2((v0 - mean) * rstd * gam[tid]       + bet[tid]);
    g_xn2[row * DIMV + tid + 256] = split_tf2((v1 - mean) * rstd * gam[tid + 256] + bet[tid + 256]);
}

// ---------------- split both weight matrices (interleaved) ----------------
__global__ void wsplit_kernel(const float* __restrict__ Wqkv, const float* __restrict__ Wout) {
    const int g4 = (blockIdx.x * 256 + threadIdx.x) * 4;
    if (g4 < 512 * 1536) {
        float4 v = *(const float4*)(Wqkv + g4);
        g_w2[g4 + 0] = split_tf2(v.x); g_w2[g4 + 1] = split_tf2(v.y);
        g_w2[g4 + 2] = split_tf2(v.z); g_w2[g4 + 3] = split_tf2(v.w);
    } else {
        const int o = g4 - 512 * 1536;
        float4 v = *(const float4*)(Wout + o);
        g_wo2[o + 0] = split_tf2(v.x); g_wo2[o + 1] = split_tf2(v.y);
        g_wo2[o + 2] = split_tf2(v.z); g_wo2[o + 3] = split_tf2(v.w);
    }
}

// ---------------- QKV GEMM: block 64x64, warp 16x32 ----------------
__global__ void __launch_bounds__(256, 4) gemm_qkv() {
    __shared__ float2 A2[16][68];
    __shared__ float2 B2[16][68];
    const int bx = blockIdx.x, by = blockIdx.y, tid = threadIdx.x;
    const int wid = tid >> 5, lane = tid & 31;
    const int wm = wid & 3, wn = wid >> 2;
    const int grp = lane >> 2, lq = lane & 3;
    const int arow = tid & 63, akq = (tid >> 6) << 2;
    float acc[4][4] = {};

    for (int k0 = 0; k0 < 512; k0 += 16) {
        const float2* ag = g_xn2 + (size_t)(by * 64 + arow) * 512 + k0 + akq;
        float4 v0 = *(const float4*)ag;
        float4 v1 = *(const float4*)(ag + 2);
        A2[akq + 0][arow] = make_float2(v0.x, v0.y);
        A2[akq + 1][arow] = make_float2(v0.z, v0.w);
        A2[akq + 2][arow] = make_float2(v1.x, v1.y);
        A2[akq + 3][arow] = make_float2(v1.z, v1.w);
#pragma unroll
        for (int c = 0; c < 4; c++)
            B2[akq + c][arow] = g_w2[(size_t)(k0 + akq + c) * 1536 + bx * 64 + arow];
        __syncthreads();
        mma_stage(A2, B2, wm, wn, grp, lq, acc);
        __syncthreads();
    }
#pragma unroll
    for (int nt = 0; nt < 4; nt++) {
        const int col = bx * 64 + wn * 32 + nt * 8 + 2 * lq;
        const int w = col >> 9, h = (col >> 6) & 7, d = col & 63;
#pragma unroll
        for (int half = 0; half < 2; half++) {
            const int row = by * 64 + wm * 16 + grp + half * 8;
            float va = acc[nt][2 * half], vb = acc[nt][2 * half + 1];
            if (w == 0) { va *= 0.125f; vb *= 0.125f; }
            float2 s0 = split_tf2(va), s1 = split_tf2(vb);
            float2* dst;
            if (w == 0)      dst = &g_q2[(h * N_TOK + row) * DH + d];
            else if (w == 1) dst = &g_k2[(h * JPAD + row + 2) * DH + d];
            else             dst = &g_v2[(h * JPAD + row + 2) * DH + d];
            *(float4*)dst = make_float4(s0.x, s0.y, s1.x, s1.y);
        }
    }
}

// ---------------- sim = q.k^T: 64x64 causal tiles ----------------
__global__ void __launch_bounds__(256, 4) sim_kernel() {
    const int f = blockIdx.x;          // 0..151
    const int h = blockIdx.y;
    int it = (int)((sqrtf(8.0f * f + 9.0f) - 3.0f) * 0.5f);
    while ((it + 1) * (it + 4) / 2 <= f) it++;
    while (it * (it + 3) / 2 > f) it--;
    const int jt = f - it * (it + 3) / 2;   // 0..it+1

    __shared__ float2 A2[16][68];
    __shared__ float2 B2[16][68];
    const int tid = threadIdx.x;
    const int wid = tid >> 5, lane = tid & 31;
    const int wm = wid & 3, wn = wid >> 2;
    const int grp = lane >> 2, lq = lane & 3;
    const int arow = tid & 63, akq = (tid >> 6) << 2;
    float acc[4][4] = {};

#pragma unroll
    for (int dc = 0; dc < 64; dc += 16) {
        const float2* qg = g_q2 + ((h << 10) + it * 64 + arow) * DH + dc + akq;
        float4 v0 = *(const float4*)qg;
        float4 v1 = *(const float4*)(qg + 2);
        A2[akq + 0][arow] = make_float2(v0.x, v0.y);
        A2[akq + 1][arow] = make_float2(v0.z, v0.w);
        A2[akq + 2][arow] = make_float2(v1.x, v1.y);
        A2[akq + 3][arow] = make_float2(v1.z, v1.w);
        const float2* kg = g_k2 + (h * JPAD + jt * 64 + arow) * DH + dc + akq;
        v0 = *(const float4*)kg;
        v1 = *(const float4*)(kg + 2);
        B2[akq + 0][arow] = make_float2(v0.x, v0.y);
        B2[akq + 1][arow] = make_float2(v0.z, v0.w);
        B2[akq + 2][arow] = make_float2(v1.x, v1.y);
        B2[akq + 3][arow] = make_float2(v1.z, v1.w);
        __syncthreads();
        mma_stage(A2, B2, wm, wn, grp, lq, acc);
        __syncthreads();
    }
#pragma unroll
    for (int nt = 0; nt < 4; nt++) {
        const int j0 = jt * 64 + wn * 32 + nt * 8 + 2 * lq;
#pragma unroll
        for (int half = 0; half < 2; half++) {
            const int i0 = it * 64 + wm * 16 + grp + half * 8;
            float* sp = g_s + (size_t)(h * N_TOK + i0) * JPAD + j0;
            *(float2*)sp = make_float2(acc[nt][2 * half], acc[nt][2 * half + 1]);
        }
    }
}

// ---------------- coordinate descent (unchanged) ----------------
template<int MAXU>
__device__ __forceinline__ void cd_row(float* __restrict__ srow, int lane, int jmax,
                                       int nchunk, int chunks) {
    float E1[MAXU];
    float tm = -3.4e38f;
#pragma unroll
    for (int u = 0; u < MAXU; u++) {
        E1[u] = -3.4e38f;
        if (u < nchunk) {
            const int j = lane + u * 32;
            if (j < jmax) { E1[u] = srow[j]; tm = fmaxf(tm, E1[u]); }
        }
    }
#pragma unroll
    for (int o = 16; o; o >>= 1) tm = fmaxf(tm, __shfl_xor_sync(0xffffffffu, tm, o));
    const float m = tm;
#pragma unroll
    for (int u = 0; u < MAXU; u++)
        if (u < nchunk)
            E1[u] = (E1[u] > -3.0e38f) ? __expf((E1[u] - m) * INV_EPS) : 0.0f;

    float a = EPSF * (LOGK - __logf((float)jmax));

    for (int it = 1; it < CD_ITERS; it++) {
        const float w = __expf((a + m) * INV_EPS);
        float ls0 = 0.0f, ls1 = 0.0f;
#pragma unroll
        for (int u = 0; u < MAXU; u++) {
            if (u < nchunk) {
                const float e = E1[u];
                const float c = fminf(e, w * (e * e));
                if (u & 1) ls1 += c; else ls0 += c;
            }
        }
        float ls = ls0 + ls1;
#pragma unroll
        for (int o = 16; o; o >>= 1) ls += __shfl_xor_sync(0xffffffffu, ls, o);
        const float a_new = EPSF * LOGK - m - EPSF * __logf(ls);
        const float da = fabsf(a_new - a);
        a = a_new;
        if (da < 5e-7f) break;
    }

    const float w = __expf((a + m) * INV_EPS);
#pragma unroll
    for (int u = 0; u < MAXU + 3; u++) {
        if (u < chunks) {
            const int j = lane + u * 32;
            float val = 0.0f;
            if (u < MAXU && u < nchunk) {
                const float eu = w * E1[u];
                val = fminf(eu, eu * eu);
            }
            srow[j] = val;
        }
    }
}

__global__ void cd_kernel() {
    const int wg   = (blockIdx.x * blockDim.x + threadIdx.x) >> 5;
    const int lane = threadIdx.x & 31;
    const int i = wg >> 3, h = wg & 7;
    const int jmax = i + 3;
    const int nchunk = (jmax + 31) >> 5;
    const int chunks = ((i >> 6) + 2) << 1;
    float* srow = g_s + (size_t)(h * N_TOK + i) * JPAD;
    if (i < 254)      cd_row<8 >(srow, lane, jmax, nchunk, chunks);
    else if (i < 510) cd_row<16>(srow, lane, jmax, nchunk, chunks);
    else if (i < 766) cd_row<24>(srow, lane, jmax, nchunk, chunks);
    else              cd_row<33>(srow, lane, jmax, nchunk, chunks);
}

// ---------------- av = attn.v: block 64x64, warp 16x32, split-K 4 ----------------
__global__ void __launch_bounds__(256, 4) av_kernel() {
    const int it = blockIdx.x;
    const int h  = blockIdx.y;
    const int sp = blockIdx.z;           // 0..3
    const int per = it + 2;              // 16-j tiles per quarter ((it+2)*4 total)
    const int jc0 = sp * per, jc1 = jc0 + per;

    __shared__ float2 A2[16][68];        // P split
    __shared__ float2 B2[16][68];        // V
    const int tid = threadIdx.x;
    const int wid = tid >> 5, lane = tid & 31;
    const int wm = wid & 3, wn = wid >> 2;
    const int grp = lane >> 2, lq = lane & 3;
    const int arow = tid & 63, akq = (tid >> 6) << 2;
    float acc[4][4] = {};

    for (int jc = jc0; jc < jc1; jc++) {
        const float* pg = g_s + (size_t)(h * N_TOK + it * 64 + arow) * JPAD + jc * 16 + akq;
        float4 p = *(const float4*)pg;
        A2[akq + 0][arow] = split_tf2(p.x);
        A2[akq + 1][arow] = split_tf2(p.y);
        A2[akq + 2][arow] = split_tf2(p.z);
        A2[akq + 3][arow] = split_tf2(p.w);
#pragma unroll
        for (int c = 0; c < 4; c++)
            B2[akq + c][arow] = g_v2[(h * JPAD + jc * 16 + akq + c) * DH + arow];
        __syncthreads();
        mma_stage(A2, B2, wm, wn, grp, lq, acc);
        __syncthreads();
    }
    float* outp = (sp == 0) ? g_o : (sp == 1) ? g_o2 : (sp == 2) ? g_o3 : g_o4;
#pragma unroll
    for (int nt = 0; nt < 4; nt++) {
        const int d = wn * 32 + nt * 8 + 2 * lq;
#pragma unroll
        for (int half = 0; half < 2; half++) {
            const int row = it * 64 + wm * 16 + grp + half * 8;
            *(float2*)(outp + row * DIMV + h * DH + d) =
                make_float2(acc[nt][2 * half], acc[nt][2 * half + 1]);
        }
    }
}

// ---------------- out projection: block 64x64, warp 16x32 ----------------
__global__ void __launch_bounds__(256, 4) gemm_proj(float* __restrict__ C) {
    __shared__ float2 A2[16][68];
    __shared__ float2 B2[16][68];
    const int bx = blockIdx.x, by = blockIdx.y, tid = threadIdx.x;
    const int wid = tid >> 5, lane = tid & 31;
    const int wm = wid & 3, wn = wid >> 2;
    const int grp = lane >> 2, lq = lane & 3;
    const int arow = tid & 63, akq = (tid >> 6) << 2;
    float acc[4][4] = {};

    for (int k0 = 0; k0 < 512; k0 += 16) {
        const int ab = (by * 64 + arow) * 512 + k0 + akq;
        float4 o1 = *(const float4*)(g_o + ab);
        float4 o2 = *(const float4*)(g_o2 + ab);
        float4 o3 = *(const float4*)(g_o3 + ab);
        float4 o4 = *(const float4*)(g_o4 + ab);
        A2[akq + 0][arow] = split_tf2((o1.x + o2.x) + (o3.x + o4.x));
        A2[akq + 1][arow] = split_tf2((o1.y + o2.y) + (o3.y + o4.y));
        A2[akq + 2][arow] = split_tf2((o1.z + o2.z) + (o3.z + o4.z));
        A2[akq + 3][arow] = split_tf2((o1.w + o2.w) + (o3.w + o4.w));
#pragma unroll
        for (int c = 0; c < 4; c++)
            B2[akq + c][arow] = g_wo2[(size_t)(k0 + akq + c) * 512 + bx * 64 + arow];
        __syncthreads();
        mma_stage(A2, B2, wm, wn, grp, lq, acc);
        __syncthreads();
    }
#pragma unroll
    for (int nt = 0; nt < 4; nt++) {
        const int col = bx * 64 + wn * 32 + nt * 8 + 2 * lq;
#pragma unroll
        for (int half = 0; half < 2; half++) {
            const int row = by * 64 + wm * 16 + grp + half * 8;
            *(float2*)(C + row * 512 + col) =
                make_float2(acc[nt][2 * half], acc[nt][2 * half + 1]);
        }
    }
}

// ---------------- launch ----------------
extern "C" void kernel_launch(void* const* d_in, const int* in_sizes, int n_in,
                              void* d_out, int out_size) {
    const float* x       = (const float*)d_in[0];
    const float* w_qkv   = (const float*)d_in[1];
    const float* w_out   = (const float*)d_in[2];
    const float* null_kv = (const float*)d_in[3];
    const float* ln_g    = (const float*)d_in[4];
    const float* ln_b    = (const float*)d_in[5];
    float* out = (float*)d_out;

    ln_fill_kernel<<<1152, 256>>>(x, ln_g, ln_b, null_kv);
    wsplit_kernel <<<1024, 256>>>(w_qkv, w_out);
    gemm_qkv      <<<dim3(24, 16), 256>>>();
    sim_kernel    <<<dim3(152, 8), 256>>>();
    cd_kernel     <<<2048, 128>>>();
    av_kernel     <<<dim3(16, 8, 4), 256>>>();
    gemm_proj     <<<dim3(8, 16), 256>>>(out);
}

// round 12
// speedup vs baseline: 1.3135x; 1.2222x over previous
#include <cuda_runtime.h>
#include <math.h>
#include <stdint.h>

#define N_TOK 1024
#define DIMV  512
#define HEADS 8
#define DH    64
#define JTOT  1026
#define JPAD  1088          // 17 * 64 = 34 * 32
#define INV_EPS 10.0f
#define EPSF    0.1f
#define LOGK    2.0794415416798357f   // log(8)
#define CD_ITERS 50

// ---------------- scratch ----------------
__device__ float g_xn[N_TOK * DIMV];
__device__ float g_q [HEADS * N_TOK * DH];
__device__ float g_k [HEADS * JPAD * DH];
__device__ float g_v [HEADS * JPAD * DH];
__device__ float g_s [HEADS * N_TOK * JPAD];
__device__ float g_o [N_TOK * DIMV];
__device__ float g_o2[N_TOK * DIMV];

// ---------------- packed f32x2 helpers ----------------
__device__ __forceinline__ void ffma2(uint64_t& acc, uint64_t a, uint64_t b) {
    asm("fma.rn.f32x2 %0, %1, %2, %0;" : "+l"(acc) : "l"(a), "l"(b));
}
__device__ __forceinline__ uint64_t bcast2(float v) {
    uint64_t r;
    const uint32_t u = __float_as_uint(v);
    asm("mov.b64 %0, {%1, %1};" : "=l"(r) : "r"(u));
    return r;
}
__device__ __forceinline__ float lo32(uint64_t v) { return __uint_as_float((uint32_t)v); }
__device__ __forceinline__ float hi32(uint64_t v) { return __uint_as_float((uint32_t)(v >> 32)); }

// ---------------- block reduction ----------------
__device__ __forceinline__ float block_sum_256(float v, float* red) {
#pragma unroll
    for (int o = 16; o; o >>= 1) v += __shfl_xor_sync(0xffffffffu, v, o);
    __syncthreads();
    if ((threadIdx.x & 31) == 0) red[threadIdx.x >> 5] = v;
    __syncthreads();
    v = red[threadIdx.x & 7];
#pragma unroll
    for (int o = 4; o; o >>= 1) v += __shfl_xor_sync(0xffffffffu, v, o);
    return v;
}

// ---------------- fused LayerNorm + null-kv/pad fill ----------------
__global__ void ln_fill_kernel(const float* __restrict__ x, const float* __restrict__ gam,
                               const float* __restrict__ bet,
                               const float* __restrict__ null_kv) {
    if (blockIdx.x >= 1024) {
        const int idx = (blockIdx.x - 1024) * 256 + threadIdx.x;
        const int h = idx >> 12;
        const int r = (idx >> 6) & 63;
        const int d = idx & 63;
        if (r < 2) {
            g_k[(h * JPAD + r) * DH + d] = null_kv[((0 * HEADS + h) * 2 + r) * DH + d];
            g_v[(h * JPAD + r) * DH + d] = null_kv[((1 * HEADS + h) * 2 + r) * DH + d];
        } else {
            const int j = 1024 + r;
            g_k[(h * JPAD + j) * DH + d] = 0.0f;
            g_v[(h * JPAD + j) * DH + d] = 0.0f;
        }
        return;
    }
    __shared__ float red[8];
    const int row = blockIdx.x;
    const int tid = threadIdx.x;
    const float v0 = x[row * DIMV + tid];
    const float v1 = x[row * DIMV + tid + 256];
    float s  = v0 + v1;
    float sq = v0 * v0 + v1 * v1;
    s  = block_sum_256(s,  red);
    sq = block_sum_256(sq, red);
    const float mean = s * (1.0f / 512.0f);
    const float var  = sq * (1.0f / 512.0f) - mean * mean;
    const float rstd = rsqrtf(var + 1e-5f);
    g_xn[row * DIMV + tid]       = (v0 - mean) * rstd * gam[tid]       + bet[tid];
    g_xn[row * DIMV + tid + 256] = (v1 - mean) * rstd * gam[tid + 256] + bet[tid + 256];
}

// ---------------- QKV GEMM: 64x64 tiles (384 blocks, residency-balanced), f32x2 -------
__global__ void gemm_qkv(const float* __restrict__ B) {
    __shared__ __align__(16) float As[16][64];
    __shared__ __align__(16) float Bs[16][64];
    const float* __restrict__ A = g_xn;
    const int bx = blockIdx.x, by = blockIdx.y, tid = threadIdx.x;
    const int tx = tid & 15, ty = tid >> 4;
    const int ar = tid >> 2, ac = (tid & 3) << 2;
    const int br = tid >> 4, bc = (tid & 15) << 2;
    uint64_t acc2[2][4] = {};   // 2 row-pairs x 4 cols

    float4 a4 = *(const float4*)(A + (by * 64 + ar) * 512 + ac);
    float4 b4 = *(const float4*)(B + (size_t)br * 1536 + bx * 64 + bc);

    for (int k0 = 0; k0 < 512; k0 += 16) {
        As[ac + 0][ar] = a4.x; As[ac + 1][ar] = a4.y;
        As[ac + 2][ar] = a4.z; As[ac + 3][ar] = a4.w;
        *(float4*)&Bs[br][bc] = b4;
        __syncthreads();
        if (k0 + 16 < 512) {
            a4 = *(const float4*)(A + (by * 64 + ar) * 512 + k0 + 16 + ac);
            b4 = *(const float4*)(B + (size_t)(k0 + 16 + br) * 1536 + bx * 64 + bc);
        }
#pragma unroll
        for (int kk = 0; kk < 16; kk++) {
            const uint64_t* ap = (const uint64_t*)&As[kk][ty << 2];
            uint64_t ra[2];
            ra[0] = ap[0]; ra[1] = ap[1];
            float4 bq = *(const float4*)&Bs[kk][tx << 2];
            uint64_t rb[4];
            rb[0] = bcast2(bq.x); rb[1] = bcast2(bq.y);
            rb[2] = bcast2(bq.z); rb[3] = bcast2(bq.w);
#pragma unroll
            for (int p = 0; p < 2; p++)
#pragma unroll
                for (int j = 0; j < 4; j++)
                    ffma2(acc2[p][j], ra[p], rb[j]);
        }
        __syncthreads();
    }
#pragma unroll
    for (int p = 0; p < 2; p++) {
#pragma unroll
        for (int j = 0; j < 4; j++) {
            const int col = bx * 64 + (tx << 2) + j;
            const int h = (col >> 6) & 7, d = col & 63, w = col >> 9;
            const int row0 = by * 64 + (ty << 2) + 2 * p;
            const float vlo = lo32(acc2[p][j]);
            const float vhi = hi32(acc2[p][j]);
            if (w == 0) {
                g_q[(h * N_TOK + row0) * DH + d]     = vlo * 0.125f;
                g_q[(h * N_TOK + row0 + 1) * DH + d] = vhi * 0.125f;
            } else if (w == 1) {
                g_k[(h * JPAD + row0 + 2) * DH + d] = vlo;
                g_k[(h * JPAD + row0 + 3) * DH + d] = vhi;
            } else {
                g_v[(h * JPAD + row0 + 2) * DH + d] = vlo;
                g_v[(h * JPAD + row0 + 3) * DH + d] = vhi;
            }
        }
    }
}

// ---------------- out projection GEMM: 64x64 tile, f32x2 pairs ------------------------
__global__ void gemm_proj(const float* __restrict__ B, float* __restrict__ C) {
    __shared__ __align__(16) float As[16][64];
    __shared__ __align__(16) float Bs[16][64];
    const int bx = blockIdx.x, by = blockIdx.y, tid = threadIdx.x;
    const int tx = tid & 15, ty = tid >> 4;
    const int ar = tid >> 2, ac = (tid & 3) << 2;
    const int br = tid >> 4, bc = (tid & 15) << 2;
    uint64_t acc2[2][4] = {};

    const int aoff0 = (by * 64 + ar) * 512 + ac;
    float4 a4 = *(const float4*)(g_o + aoff0);
    float4 a4b = *(const float4*)(g_o2 + aoff0);
    a4.x += a4b.x; a4.y += a4b.y; a4.z += a4b.z; a4.w += a4b.w;
    float4 b4 = *(const float4*)(B + (size_t)br * 512 + bx * 64 + bc);

    for (int k0 = 0; k0 < 512; k0 += 16) {
        As[ac + 0][ar] = a4.x; As[ac + 1][ar] = a4.y;
        As[ac + 2][ar] = a4.z; As[ac + 3][ar] = a4.w;
        *(float4*)&Bs[br][bc] = b4;
        __syncthreads();
        if (k0 + 16 < 512) {
            const int aoff = (by * 64 + ar) * 512 + k0 + 16 + ac;
            a4 = *(const float4*)(g_o + aoff);
            a4b = *(const float4*)(g_o2 + aoff);
            a4.x += a4b.x; a4.y += a4b.y; a4.z += a4b.z; a4.w += a4b.w;
            b4 = *(const float4*)(B + (size_t)(k0 + 16 + br) * 512 + bx * 64 + bc);
        }
#pragma unroll
        for (int kk = 0; kk < 16; kk++) {
            const uint64_t* ap = (const uint64_t*)&As[kk][ty << 2];
            uint64_t ra[2];
            ra[0] = ap[0]; ra[1] = ap[1];
            float4 bq = *(const float4*)&Bs[kk][tx << 2];
            uint64_t rb[4];
            rb[0] = bcast2(bq.x); rb[1] = bcast2(bq.y);
            rb[2] = bcast2(bq.z); rb[3] = bcast2(bq.w);
#pragma unroll
            for (int p = 0; p < 2; p++)
#pragma unroll
                for (int j = 0; j < 4; j++)
                    ffma2(acc2[p][j], ra[p], rb[j]);
        }
        __syncthreads();
    }
#pragma unroll
    for (int p = 0; p < 2; p++) {
        const int row0 = by * 64 + (ty << 2) + 2 * p;
        const int colb = bx * 64 + (tx << 2);
        C[row0 * 512 + colb + 0] = lo32(acc2[p][0]);
        C[row0 * 512 + colb + 1] = lo32(acc2[p][1]);
        C[row0 * 512 + colb + 2] = lo32(acc2[p][2]);
        C[row0 * 512 + colb + 3] = lo32(acc2[p][3]);
        C[(row0 + 1) * 512 + colb + 0] = hi32(acc2[p][0]);
        C[(row0 + 1) * 512 + colb + 1] = hi32(acc2[p][1]);
        C[(row0 + 1) * 512 + colb + 2] = hi32(acc2[p][2]);
        C[(row0 + 1) * 512 + colb + 3] = hi32(acc2[p][3]);
    }
}

// ---------------- sim = q . k^T: 128(i) x 64(j) tiles, f32x2 pairs --------------------
__global__ void sim_kernel() {
    const int f = blockIdx.x;
    const int h = blockIdx.y;
    int it2 = __float2int_rd(sqrtf((float)(f + 1))) - 1;
    while ((it2 + 1) * (it2 + 3) <= f) it2++;
    while (it2 * (it2 + 2) > f) it2--;
    const int jt = f - it2 * (it2 + 2);

    __shared__ __align__(16) float Qs[32][132];
    __shared__ __align__(16) float Ks[32][68];
    const int tid = threadIdx.x;
    const int tx = tid & 15, ty = tid >> 4;
    uint64_t acc2[4][4] = {};   // 4 i-pairs x 4 j

#pragma unroll
    for (int dc = 0; dc < 64; dc += 32) {
        {
            const int row = tid >> 1;
            const int base = ((h << 10) + it2 * 128 + row) * DH + dc + ((tid & 1) << 4);
#pragma unroll
            for (int t = 0; t < 4; t++) {
                float4 q4 = *(const float4*)&g_q[base + t * 4];
                const int off = ((tid & 1) << 4) + t * 4;
                Qs[off + 0][row] = q4.x; Qs[off + 1][row] = q4.y;
                Qs[off + 2][row] = q4.z; Qs[off + 3][row] = q4.w;
            }
        }
        {
            const int row = tid >> 2;
            const int base = (h * JPAD + jt * 64 + row) * DH + dc + ((tid & 3) << 3);
#pragma unroll
            for (int t = 0; t < 2; t++) {
                float4 k4 = *(const float4*)&g_k[base + t * 4];
                const int off = ((tid & 3) << 3) + t * 4;
                Ks[off + 0][row] = k4.x; Ks[off + 1][row] = k4.y;
                Ks[off + 2][row] = k4.z; Ks[off + 3][row] = k4.w;
            }
        }
        __syncthreads();
#pragma unroll 8
        for (int d = 0; d < 32; d++) {
            const uint64_t* ap = (const uint64_t*)&Qs[d][ty << 3];
            uint64_t ra[4];
            ra[0] = ap[0]; ra[1] = ap[1]; ra[2] = ap[2]; ra[3] = ap[3];
            float4 kq = *(const float4*)&Ks[d][tx << 2];
            uint64_t rb[4];
            rb[0] = bcast2(kq.x); rb[1] = bcast2(kq.y);
            rb[2] = bcast2(kq.z); rb[3] = bcast2(kq.w);
#pragma unroll
            for (int p = 0; p < 4; p++)
#pragma unroll
                for (int j = 0; j < 4; j++)
                    ffma2(acc2[p][j], ra[p], rb[j]);
        }
        __syncthreads();
    }
#pragma unroll
    for (int p = 0; p < 4; p++) {
        const int i0 = it2 * 128 + (ty << 3) + 2 * p;
        float* sr0 = g_s + (size_t)(h * N_TOK + i0) * JPAD + jt * 64 + (tx << 2);
        float* sr1 = sr0 + JPAD;
        *(float4*)sr0 = make_float4(lo32(acc2[p][0]), lo32(acc2[p][1]),
                                    lo32(acc2[p][2]), lo32(acc2[p][3]));
        *(float4*)sr1 = make_float4(hi32(acc2[p][0]), hi32(acc2[p][1]),
                                    hi32(acc2[p][2]), hi32(acc2[p][3]));
    }
}

// ---------------- coordinate descent (unchanged round-5/7) ----------------
template<int MAXU>
__device__ __forceinline__ void cd_row(float* __restrict__ srow, int lane, int jmax,
                                       int nchunk, int chunks) {
    float E1[MAXU];
    float tm = -3.4e38f;
#pragma unroll
    for (int u = 0; u < MAXU; u++) {
        E1[u] = -3.4e38f;
        if (u < nchunk) {
            const int j = lane + u * 32;
            if (j < jmax) { E1[u] = srow[j]; tm = fmaxf(tm, E1[u]); }
        }
    }
#pragma unroll
    for (int o = 16; o; o >>= 1) tm = fmaxf(tm, __shfl_xor_sync(0xffffffffu, tm, o));
    const float m = tm;
#pragma unroll
    for (int u = 0; u < MAXU; u++)
        if (u < nchunk)
            E1[u] = (E1[u] > -3.0e38f) ? __expf((E1[u] - m) * INV_EPS) : 0.0f;

    float a = EPSF * (LOGK - __logf((float)jmax));

    for (int it = 1; it < CD_ITERS; it++) {
        const float w = __expf((a + m) * INV_EPS);
        float ls0 = 0.0f, ls1 = 0.0f;
#pragma unroll
        for (int u = 0; u < MAXU; u++) {
            if (u < nchunk) {
                const float e = E1[u];
                const float c = fminf(e, w * (e * e));
                if (u & 1) ls1 += c; else ls0 += c;
            }
        }
        float ls = ls0 + ls1;
#pragma unroll
        for (int o = 16; o; o >>= 1) ls += __shfl_xor_sync(0xffffffffu, ls, o);
        const float a_new = EPSF * LOGK - m - EPSF * __logf(ls);
        const float da = fabsf(a_new - a);
        a = a_new;
        if (da < 5e-7f) break;
    }

    const float w = __expf((a + m) * INV_EPS);
#pragma unroll
    for (int u = 0; u < MAXU + 3; u++) {
        if (u < chunks) {
            const int j = lane + u * 32;
            float val = 0.0f;
            if (u < MAXU && u < nchunk) {
                const float eu = w * E1[u];
                val = fminf(eu, eu * eu);
            }
            srow[j] = val;
        }
    }
}

__global__ void cd_kernel() {
    const int wg   = (blockIdx.x * blockDim.x + threadIdx.x) >> 5;
    const int lane = threadIdx.x & 31;
    const int i = wg >> 3, h = wg & 7;
    const int jmax = i + 3;
    const int nchunk = (jmax + 31) >> 5;
    const int chunks = ((i >> 6) + 2) << 1;
    float* srow = g_s + (size_t)(h * N_TOK + i) * JPAD;
    if (i < 254)      cd_row<8 >(srow, lane, jmax, nchunk, chunks);
    else if (i < 510) cd_row<16>(srow, lane, jmax, nchunk, chunks);
    else if (i < 766) cd_row<24>(srow, lane, jmax, nchunk, chunks);
    else              cd_row<33>(srow, lane, jmax, nchunk, chunks);
}

// ---------------- out = attn . v : split-K over j, f32x2 pairs ------------------------
__global__ void av_kernel() {
    const int it = blockIdx.x;
    const int h  = blockIdx.y;
    const int sp = blockIdx.z;
    const int T = it + 2;
    const int half = T >> 1;
    const int j0 = sp ? half : 0;
    const int j1 = sp ? T : half;
    __shared__ __align__(16) float Ps[64][66];
    __shared__ __align__(16) float Vs[64][64];
    const int tid = threadIdx.x;
    const int tx = tid & 15, ty = tid >> 4;
    const int c = (tid & 15) << 2;
    uint64_t acc2[2][4] = {};   // 2 i-pairs x 4 d
    for (int jt = j0; jt < j1; jt++) {
#pragma unroll
        for (int t = 0; t < 4; t++) {
            const int r = (tid >> 4) + t * 16;
            float4 p4 = *(const float4*)&g_s[(size_t)(h * N_TOK + it * 64 + r) * JPAD + jt * 64 + c];
            Ps[c + 0][r] = p4.x; Ps[c + 1][r] = p4.y; Ps[c + 2][r] = p4.z; Ps[c + 3][r] = p4.w;
            float4 v4 = *(const float4*)&g_v[(h * JPAD + jt * 64 + r) * DH + c];
            *(float4*)&Vs[r][c] = v4;
        }
        __syncthreads();
#pragma unroll 16
        for (int j = 0; j < 64; j++) {
            const uint64_t* ap = (const uint64_t*)&Ps[j][ty << 2];
            uint64_t ra[2];
            ra[0] = ap[0]; ra[1] = ap[1];
            float4 vq = *(const float4*)&Vs[j][tx << 2];
            uint64_t rb[4];
            rb[0] = bcast2(vq.x); rb[1] = bcast2(vq.y);
            rb[2] = bcast2(vq.z); rb[3] = bcast2(vq.w);
#pragma unroll
            for (int p = 0; p < 2; p++)
#pragma unroll
                for (int jj = 0; jj < 4; jj++)
                    ffma2(acc2[p][jj], ra[p], rb[jj]);
        }
        __syncthreads();
    }
    float* outp = sp ? g_o2 : g_o;
#pragma unroll
    for (int p = 0; p < 2; p++) {
        const int row0 = it * 64 + (ty << 2) + 2 * p;
        float* o0 = outp + row0 * DIMV + h * DH + (tx << 2);
        float* o1 = o0 + DIMV;
        *(float4*)o0 = make_float4(lo32(acc2[p][0]), lo32(acc2[p][1]),
                                   lo32(acc2[p][2]), lo32(acc2[p][3]));
        *(float4*)o1 = make_float4(hi32(acc2[p][0]), hi32(acc2[p][1]),
                                   hi32(acc2[p][2]), hi32(acc2[p][3]));
    }
}

// ---------------- launch ----------------
extern "C" void kernel_launch(void* const* d_in, const int* in_sizes, int n_in,
                              void* d_out, int out_size) {
    const float* x       = (const float*)d_in[0];
    const float* w_qkv   = (const float*)d_in[1];
    const float* w_out   = (const float*)d_in[2];
    const float* null_kv = (const float*)d_in[3];
    const float* ln_g    = (const float*)d_in[4];
    const float* ln_b    = (const float*)d_in[5];
    float* out = (float*)d_out;

    ln_fill_kernel<<<1152, 256>>>(x, ln_g, ln_b, null_kv);
    gemm_qkv   <<<dim3(24, 16), 256>>>(w_qkv);
    sim_kernel <<<dim3(80, HEADS), 256>>>();
    cd_kernel  <<<2048, 128>>>();
    av_kernel  <<<dim3(16, HEADS, 2), 256>>>();
    gemm_proj  <<<dim3(8, 16), 256>>>(w_out, out);
}